// round 13
// baseline (speedup 1.0000x reference)
#include <cuda_runtime.h>
#include <math.h>

// Problem constants (fixed shapes from reference setup_inputs)
#define BATCH 4
#define NPTS  8192
#define ALPHA 1000.0f

// 2D serpentine column grid on (x,y): 64x64 cells of width 0.125 on [-4,4).
#define GDIM   64
#define CELLW  0.125f
#define NCOL   (GDIM * GDIM)
#define KRECT  2
#define MARGIN 1e-4f
#define BIG    3.0e38f

// ---------------------------------------------------------------------------
// Scratch (__device__ globals; zero-initialized at module load).
// Self-cleaning invariants across graph replays:
//   g_hist == 0  (restored by scan kernel after reading)
//   g_cnt  == 0  (zeroed by hist kernel at the start of each call)
//   g_fbn  == 0  (reset by scatter kernel, before pass A runs)
// arr index a: 0 = xyz1 (pred), 1 = xyz2 (gt)
// ---------------------------------------------------------------------------
__device__ float4 g_pts   [2][BATCH][NPTS];      // column-sorted (x,y,z,|p|^2)
__device__ int    g_orig  [2][BATCH][NPTS];
__device__ int    g_colid [2][BATCH][NPTS];
__device__ int    g_hist  [2][BATCH][NCOL];
__device__ int    g_start [2][BATCH][NCOL + 1];
__device__ int    g_cursor[2][BATCH][NCOL];
// dir 0: queries = xyz2 (gt), refs = xyz1 (pred); dir 1: swapped
__device__ float  g_dist[2][BATCH][NPTS];
__device__ int    g_idx [2][BATCH][NPTS];
__device__ int    g_cnt [2][BATCH][NPTS];
// fallback queue: packed (dir<<15 | b<<13 | si)
__device__ int    g_fbq[2 * BATCH * NPTS];
__device__ int    g_fbn;

__device__ __forceinline__ int cell_coord(float x) {
    int c = (int)floorf(x * 8.0f) + 32;
    return min(GDIM - 1, max(0, c));
}
__device__ __forceinline__ int serp_col(int cx, int cy) {
    return cx * GDIM + ((cx & 1) ? (GDIM - 1 - cy) : cy);
}
__device__ __forceinline__ float cell_lo(int c) {
    return (float)c * CELLW - 4.0f;
}

// ---------------------------------------------------------------------------
// K1: zero g_cnt + out, serpentine column ids + histogram
// ---------------------------------------------------------------------------
__global__ void dacd_hist_kernel(const float* __restrict__ xyz1,
                                 const float* __restrict__ xyz2,
                                 float* __restrict__ out) {
    int t = blockIdx.x * blockDim.x + threadIdx.x;
    if (t >= 2 * BATCH * NPTS) return;
    ((int*)g_cnt)[t] = 0;
    if (t == 0) out[0] = 0.0f;
    const int a   = t / (BATCH * NPTS);
    const int rem = t % (BATCH * NPTS);
    const int b   = rem / NPTS;
    const int j   = rem % NPTS;
    const float* src = (a == 0) ? xyz1 : xyz2;
    float x = src[((size_t)b * NPTS + j) * 3 + 0];
    float y = src[((size_t)b * NPTS + j) * 3 + 1];
    int col = serp_col(cell_coord(x), cell_coord(y));
    g_colid[a][b][j] = col;
    atomicAdd(&g_hist[a][b][col], 1);
}

// ---------------------------------------------------------------------------
// K2: exclusive scan of 4096-entry histogram per set, then restore g_hist=0
// ---------------------------------------------------------------------------
__global__ void __launch_bounds__(1024)
dacd_scan_kernel() {
    const int a = blockIdx.x >> 2;
    const int b = blockIdx.x & 3;
    const int tid  = threadIdx.x;
    const int lane = tid & 31;
    const int wid  = tid >> 5;
    __shared__ int ws[32];

    int h[4];
    int tot = 0;
    #pragma unroll
    for (int i = 0; i < 4; i++) {
        h[i] = g_hist[a][b][tid * 4 + i];
        tot += h[i];
    }
    int v = tot;
    #pragma unroll
    for (int off = 1; off < 32; off <<= 1) {
        int u = __shfl_up_sync(0xFFFFFFFFu, v, off);
        if (lane >= off) v += u;
    }
    if (lane == 31) ws[wid] = v;
    __syncthreads();
    if (wid == 0) {
        int s = ws[lane];
        #pragma unroll
        for (int off = 1; off < 32; off <<= 1) {
            int u = __shfl_up_sync(0xFFFFFFFFu, s, off);
            if (lane >= off) s += u;
        }
        ws[lane] = s;
    }
    __syncthreads();
    int base = (wid > 0 ? ws[wid - 1] : 0) + v - tot;
    #pragma unroll
    for (int i = 0; i < 4; i++) {
        g_start [a][b][tid * 4 + i] = base;
        g_cursor[a][b][tid * 4 + i] = base;
        base += h[i];
        g_hist[a][b][tid * 4 + i] = 0;                  // restore invariant
    }
    if (tid == 1023) g_start[a][b][NCOL] = base;        // == NPTS
}

// ---------------------------------------------------------------------------
// K3: scatter points into serpentine-column-sorted order; reset queue count
// ---------------------------------------------------------------------------
__global__ void dacd_scatter_kernel(const float* __restrict__ xyz1,
                                    const float* __restrict__ xyz2) {
    int t = blockIdx.x * blockDim.x + threadIdx.x;
    if (t >= 2 * BATCH * NPTS) return;
    if (t == 0) g_fbn = 0;
    const int a   = t / (BATCH * NPTS);
    const int rem = t % (BATCH * NPTS);
    const int b   = rem / NPTS;
    const int j   = rem % NPTS;
    const float* src = (a == 0) ? xyz1 : xyz2;
    float x = src[((size_t)b * NPTS + j) * 3 + 0];
    float y = src[((size_t)b * NPTS + j) * 3 + 1];
    float z = src[((size_t)b * NPTS + j) * 3 + 2];
    int col = g_colid[a][b][j];
    int pos = atomicAdd(&g_cursor[a][b][col], 1);
    g_pts [a][b][pos] = make_float4(x, y, z, x * x + y * y + z * z);
    g_orig[a][b][pos] = j;
}

// ---------------------------------------------------------------------------
// K4a: pass A — dense thread-per-query rect scan, rows SPLIT across 2 warps.
// Group = 32 consecutive sorted queries; warps (2g, 2g+1) both hold the same
// 32 queries (lane i = query i) and scan disjoint halves of the rect's
// serpentine row-runs. Row bounds are prefetched lane-parallel and shuffled
// (no serial cs[] chain). Inner loop: broadcast LDG.128 + 3 FFMA + FMNMX.
// Halves merge per-lane via smem. Exactness: unscanned points lie outside the
// rect, hence differ from q by >= distance-to-rect-boundary in x or y
// (grid-clamped sides have no unscanned points); lanes meeting the bound
// finalize via winner-run replay (min original index among d==bestd), the
// rest are queued.
// ---------------------------------------------------------------------------
__global__ void __launch_bounds__(256)
dacd_nn_grid_kernel() {
    const int lane   = threadIdx.x & 31;
    const int wlocal = threadIdx.x >> 5;                 // 0..7
    const int gw     = blockIdx.x * 8 + wlocal;          // 0..4095
    const int group  = gw >> 1;                          // 0..2047
    const int half   = gw & 1;
    const int dir    = group >> 10;
    const int b      = (group >> 8) & 3;
    const int chunk  = group & 255;
    const int qarr   = 1 - dir;
    const int rarr   = dir;

    const int si = chunk * 32 + lane;
    const float4 q  = g_pts [qarr][b][si];
    const int    oi = g_orig[qarr][b][si];
    const float mx = -2.0f * q.x, my = -2.0f * q.y, mz = -2.0f * q.z;

    const int qcx = cell_coord(q.x);
    const int qcy = cell_coord(q.y);
    const int bx0 = (int)__reduce_min_sync(0xFFFFFFFFu, (unsigned)qcx);
    const int bx1 = (int)__reduce_max_sync(0xFFFFFFFFu, (unsigned)qcx);
    const int by0 = (int)__reduce_min_sync(0xFFFFFFFFu, (unsigned)qcy);
    const int by1 = (int)__reduce_max_sync(0xFFFFFFFFu, (unsigned)qcy);

    const int xlo = max(bx0 - KRECT, 0), xhi = min(bx1 + KRECT, GDIM - 1);
    const int ylo = max(by0 - KRECT, 0), yhi = min(by1 + KRECT, GDIM - 1);
    const int R   = xhi - xlo + 1;                       // rows (>= 5)

    const float4* __restrict__ refs = &g_pts  [rarr][b][0];
    const int*    __restrict__ cs   = &g_start[rarr][b][0];

    // lane-parallel row-bound prefetch (row xlo+lane), broadcast via shuffle
    int srow = 0, erow = 0;
    if (lane < R) {
        const int cx = xlo + lane;
        int lo, hi;
        if (cx & 1) { lo = cx * GDIM + (GDIM - 1 - yhi); hi = cx * GDIM + (GDIM - 1 - ylo); }
        else        { lo = cx * GDIM + ylo;              hi = cx * GDIM + yhi; }
        srow = cs[lo];
        erow = cs[hi + 1];
    }

    const int r0 = (R * half) >> 1;
    const int r1 = (R * (half + 1)) >> 1;

    float bestd = INFINITY;        // d' = |r|^2 - 2 q.r
    int   runs = 0, rune = 0;      // winning run bounds

    #pragma unroll 1
    for (int r = r0; r < r1; r++) {
        const int s = __shfl_sync(0xFFFFFFFFu, srow, r);
        const int e = __shfl_sync(0xFFFFFFFFu, erow, r);
        const float pre = bestd;
        #pragma unroll 4
        for (int t = s; t < e; t++) {
            float4 v = __ldg(&refs[t]);
            float d = fmaf(mx, v.x, fmaf(my, v.y, fmaf(mz, v.z, v.w)));
            bestd = fminf(bestd, d);
        }
        if (bestd < pre) { runs = s; rune = e; }
    }

    // merge the two halves per-lane through shared memory
    __shared__ float sd[8][32];
    __shared__ int   ss[8][32], se[8][32];
    sd[wlocal][lane] = bestd;
    ss[wlocal][lane] = runs;
    se[wlocal][lane] = rune;
    __syncthreads();

    if (half == 0) {
        const float od = sd[wlocal + 1][lane];
        if (od < bestd) {
            bestd = od; runs = ss[wlocal + 1][lane]; rune = se[wlocal + 1][lane];
        } else if (od == bestd && ss[wlocal + 1][lane] < runs) {
            runs = ss[wlocal + 1][lane]; rune = se[wlocal + 1][lane];
        }

        // per-lane escape bound
        float sx0 = (xlo > 0)        ? (q.x - cell_lo(xlo))     : BIG;
        float sx1 = (xhi < GDIM - 1) ? (cell_lo(xhi + 1) - q.x) : BIG;
        float sy0 = (ylo > 0)        ? (q.y - cell_lo(ylo))     : BIG;
        float sy1 = (yhi < GDIM - 1) ? (cell_lo(yhi + 1) - q.y) : BIG;
        float bb = fminf(fminf(sx0, sx1), fminf(sy0, sy1));
        const bool ok = (q.w + bestd) <= (bb * bb - MARGIN);

        if (ok) {
            // replay winning run: min ORIGINAL index among d == bestd
            int bj = 0x7FFFFFFF;
            #pragma unroll 4
            for (int t = runs; t < rune; t++) {
                float4 v = refs[t];
                float d = fmaf(mx, v.x, fmaf(my, v.y, fmaf(mz, v.z, v.w)));
                if (d == bestd) bj = min(bj, g_orig[rarr][b][t]);
            }
            g_dist[dir][b][oi] = q.w + bestd;
            g_idx [dir][b][oi] = bj;
            atomicAdd(&g_cnt[dir][b][bj], 1);
        }
        const unsigned vote = __ballot_sync(0xFFFFFFFFu, !ok);
        if (vote) {
            int base = 0;
            if (lane == 0) base = atomicAdd(&g_fbn, __popc(vote));
            base = __shfl_sync(0xFFFFFFFFu, base, 0);
            if (!ok) {
                int off = __popc(vote & ((1u << lane) - 1u));
                g_fbq[base + off] = (dir << 15) | (b << 13) | si;
            }
        }
    }
}

// ---------------------------------------------------------------------------
// K4b: pass B — expanding-rectangle exact NN for queued queries (warp/query,
// grid-strided), k in {6,14,63}. k=63 covers the grid: guaranteed exact.
// ---------------------------------------------------------------------------
__global__ void __launch_bounds__(256)
dacd_nn_fallback_kernel() {
    const int lane = threadIdx.x & 31;
    const int wid  = blockIdx.x * 8 + (threadIdx.x >> 5);
    const int nw   = gridDim.x * 8;
    const int n    = g_fbn;

    const int KS[3] = {6, 14, 63};

    for (int item = wid; item < n; item += nw) {
        const int pk  = g_fbq[item];
        const int dir = pk >> 15;
        const int b   = (pk >> 13) & 3;
        const int si  = pk & 0x1FFF;
        const int qarr = 1 - dir;
        const int rarr = dir;

        const float4 q  = g_pts [qarr][b][si];
        const int    oi = g_orig[qarr][b][si];
        const float mx = -2.0f * q.x, my = -2.0f * q.y, mz = -2.0f * q.z;
        const int cx0 = cell_coord(q.x);
        const int cy0 = cell_coord(q.y);

        const float4* __restrict__ refs = &g_pts  [rarr][b][0];
        const int*    __restrict__ cs   = &g_start[rarr][b][0];

        #pragma unroll 1
        for (int ki = 0; ki < 3; ki++) {
            const int k = KS[ki];
            const int xlo = max(cx0 - k, 0), xhi = min(cx0 + k, GDIM - 1);
            const int ylo = max(cy0 - k, 0), yhi = min(cy0 + k, GDIM - 1);

            float bestd = INFINITY;
            int   bestt = 0;
            #pragma unroll 1
            for (int cx = xlo; cx <= xhi; cx++) {
                int lo, hi;
                if (cx & 1) { lo = cx * GDIM + (GDIM - 1 - yhi); hi = cx * GDIM + (GDIM - 1 - ylo); }
                else        { lo = cx * GDIM + ylo;              hi = cx * GDIM + yhi; }
                const int s = cs[lo];
                const int e = cs[hi + 1];
                for (int t = s + lane; t < e; t += 32) {
                    float4 v = __ldg(&refs[t]);
                    float d = fmaf(mx, v.x, fmaf(my, v.y, fmaf(mz, v.z, v.w)));
                    if (d < bestd || (d == bestd && t < bestt)) { bestd = d; bestt = t; }
                }
            }
            #pragma unroll
            for (int off = 16; off > 0; off >>= 1) {
                float od = __shfl_xor_sync(0xFFFFFFFFu, bestd, off);
                int   ot = __shfl_xor_sync(0xFFFFFFFFu, bestt, off);
                if (od < bestd || (od == bestd && ot < bestt)) { bestd = od; bestt = ot; }
            }
            float sx0 = (xlo > 0)        ? (q.x - cell_lo(xlo))     : BIG;
            float sx1 = (xhi < GDIM - 1) ? (cell_lo(xhi + 1) - q.x) : BIG;
            float sy0 = (ylo > 0)        ? (q.y - cell_lo(ylo))     : BIG;
            float sy1 = (yhi < GDIM - 1) ? (cell_lo(yhi + 1) - q.y) : BIG;
            float bb = fminf(fminf(sx0, sx1), fminf(sy0, sy1));
            const bool covered = (xlo == 0 && ylo == 0 && xhi == GDIM - 1 && yhi == GDIM - 1);
            if ((q.w + bestd) <= (bb * bb - MARGIN) || covered) {
                if (lane == 0) {
                    const int bj = g_orig[rarr][b][bestt];
                    g_dist[dir][b][oi] = q.w + bestd;
                    g_idx [dir][b][oi] = bj;
                    atomicAdd(&g_cnt[dir][b][bj], 1);
                }
                break;
            }
        }
    }
}

// ---------------------------------------------------------------------------
// K5: density-aware weighting + reduction to scalar.
// frac_21 = 1.0 exactly; ceil(frac_21) = 1.
// weight1 = 1 / max(1/c + 1e-6, 1),  weight2 = 1 / (c + 1e-6)
// out = sum (1 - exp(-alpha*d) * w) / (2*B*N)
// ---------------------------------------------------------------------------
__global__ void __launch_bounds__(256)
dacd_loss_kernel(float* __restrict__ out) {
    const int t = blockIdx.x * blockDim.x + threadIdx.x;
    const int dir = t / (BATCH * NPTS);
    const int rem = t % (BATCH * NPTS);
    const int b = rem / NPTS;
    const int i = rem % NPTS;

    float dist = g_dist[dir][b][i];
    int   idx  = g_idx [dir][b][i];
    float c    = (float)g_cnt[dir][b][idx];

    float w;
    if (dir == 0) {
        w = 1.0f / fmaxf(1.0f / c + 1e-6f, 1.0f);
    } else {
        w = 1.0f / (c + 1e-6f);
    }

    float e = expf(-dist * ALPHA);
    float contrib = (1.0f - e * w) * (1.0f / (2.0f * BATCH * NPTS));

    #pragma unroll
    for (int off = 16; off > 0; off >>= 1)
        contrib += __shfl_down_sync(0xFFFFFFFFu, contrib, off);

    __shared__ float warp_sums[8];
    const int lane = threadIdx.x & 31;
    const int wid  = threadIdx.x >> 5;
    if (lane == 0) warp_sums[wid] = contrib;
    __syncthreads();

    if (wid == 0) {
        float s = (lane < 8) ? warp_sums[lane] : 0.0f;
        #pragma unroll
        for (int off = 4; off > 0; off >>= 1)
            s += __shfl_down_sync(0xFFFFFFFFu, s, off);
        if (lane == 0) atomicAdd(out, s);
    }
}

// ---------------------------------------------------------------------------
// Launch
// ---------------------------------------------------------------------------
extern "C" void kernel_launch(void* const* d_in, const int* in_sizes, int n_in,
                              void* d_out, int out_size) {
    const float* xyz1 = (const float*)d_in[0];  // prediction [4,8192,3]
    const float* xyz2 = (const float*)d_in[1];  // ground truth [4,8192,3]
    float* out = (float*)d_out;

    (void)in_sizes; (void)n_in; (void)out_size;

    const int total = 2 * BATCH * NPTS;          // 65536

    dacd_hist_kernel    <<<(total + 255) / 256, 256>>>(xyz1, xyz2, out);
    dacd_scan_kernel    <<<2 * BATCH, 1024>>>();
    dacd_scatter_kernel <<<(total + 255) / 256, 256>>>(xyz1, xyz2);

    dacd_nn_grid_kernel    <<<512, 256>>>();     // 4096 warps: 2 per 32 queries
    dacd_nn_fallback_kernel<<<256, 256>>>();     // 2048 warps, queue-strided

    dacd_loss_kernel<<<total / 256, 256>>>(out);
}

// round 14
// speedup vs baseline: 1.1650x; 1.1650x over previous
#include <cuda_runtime.h>
#include <math.h>

// Problem constants (fixed shapes from reference setup_inputs)
#define BATCH 4
#define NPTS  8192
#define ALPHA 1000.0f

// 2D serpentine column grid on (x,y): 64x64 cells of width 0.125 on [-4,4).
#define GDIM   64
#define CELLW  0.125f
#define NCOL   (GDIM * GDIM)
#define MARGIN 1e-4f
#define BIG    3.0e38f

// ---------------------------------------------------------------------------
// Scratch (__device__ globals; zero-initialized at module load).
// Self-cleaning invariants across graph replays:
//   g_hist == 0  (restored by scan kernel after reading)
//   g_cnt  == 0  (zeroed by hist kernel at the start of each call)
// arr index a: 0 = xyz1 (pred), 1 = xyz2 (gt)
// ---------------------------------------------------------------------------
__device__ float4 g_pts   [2][BATCH][NPTS];      // column-sorted (x,y,z,|p|^2)
__device__ int    g_orig  [2][BATCH][NPTS];
__device__ int    g_colid [2][BATCH][NPTS];
__device__ int    g_hist  [2][BATCH][NCOL];
__device__ int    g_start [2][BATCH][NCOL + 1];
__device__ int    g_cursor[2][BATCH][NCOL];
// dir 0: queries = xyz2 (gt), refs = xyz1 (pred); dir 1: swapped
__device__ float  g_dist[2][BATCH][NPTS];
__device__ int    g_idx [2][BATCH][NPTS];
__device__ int    g_cnt [2][BATCH][NPTS];

__device__ __forceinline__ int cell_coord(float x) {
    int c = (int)floorf(x * 8.0f) + 32;
    return min(GDIM - 1, max(0, c));
}
__device__ __forceinline__ int serp_col(int cx, int cy) {
    return cx * GDIM + ((cx & 1) ? (GDIM - 1 - cy) : cy);
}
__device__ __forceinline__ float cell_lo(int c) {
    return (float)c * CELLW - 4.0f;
}

// ---------------------------------------------------------------------------
// K1: zero g_cnt + out, serpentine column ids + histogram
// ---------------------------------------------------------------------------
__global__ void dacd_hist_kernel(const float* __restrict__ xyz1,
                                 const float* __restrict__ xyz2,
                                 float* __restrict__ out) {
    int t = blockIdx.x * blockDim.x + threadIdx.x;
    if (t >= 2 * BATCH * NPTS) return;
    ((int*)g_cnt)[t] = 0;
    if (t == 0) out[0] = 0.0f;
    const int a   = t / (BATCH * NPTS);
    const int rem = t % (BATCH * NPTS);
    const int b   = rem / NPTS;
    const int j   = rem % NPTS;
    const float* src = (a == 0) ? xyz1 : xyz2;
    float x = src[((size_t)b * NPTS + j) * 3 + 0];
    float y = src[((size_t)b * NPTS + j) * 3 + 1];
    int col = serp_col(cell_coord(x), cell_coord(y));
    g_colid[a][b][j] = col;
    atomicAdd(&g_hist[a][b][col], 1);
}

// ---------------------------------------------------------------------------
// K2: exclusive scan of 4096-entry histogram per set, then restore g_hist=0
// ---------------------------------------------------------------------------
__global__ void __launch_bounds__(1024)
dacd_scan_kernel() {
    const int a = blockIdx.x >> 2;
    const int b = blockIdx.x & 3;
    const int tid  = threadIdx.x;
    const int lane = tid & 31;
    const int wid  = tid >> 5;
    __shared__ int ws[32];

    int h[4];
    int tot = 0;
    #pragma unroll
    for (int i = 0; i < 4; i++) {
        h[i] = g_hist[a][b][tid * 4 + i];
        tot += h[i];
    }
    int v = tot;
    #pragma unroll
    for (int off = 1; off < 32; off <<= 1) {
        int u = __shfl_up_sync(0xFFFFFFFFu, v, off);
        if (lane >= off) v += u;
    }
    if (lane == 31) ws[wid] = v;
    __syncthreads();
    if (wid == 0) {
        int s = ws[lane];
        #pragma unroll
        for (int off = 1; off < 32; off <<= 1) {
            int u = __shfl_up_sync(0xFFFFFFFFu, s, off);
            if (lane >= off) s += u;
        }
        ws[lane] = s;
    }
    __syncthreads();
    int base = (wid > 0 ? ws[wid - 1] : 0) + v - tot;
    #pragma unroll
    for (int i = 0; i < 4; i++) {
        g_start [a][b][tid * 4 + i] = base;
        g_cursor[a][b][tid * 4 + i] = base;
        base += h[i];
        g_hist[a][b][tid * 4 + i] = 0;                  // restore invariant
    }
    if (tid == 1023) g_start[a][b][NCOL] = base;        // == NPTS
}

// ---------------------------------------------------------------------------
// K3: scatter points into serpentine-column-sorted order
// ---------------------------------------------------------------------------
__global__ void dacd_scatter_kernel(const float* __restrict__ xyz1,
                                    const float* __restrict__ xyz2) {
    int t = blockIdx.x * blockDim.x + threadIdx.x;
    if (t >= 2 * BATCH * NPTS) return;
    const int a   = t / (BATCH * NPTS);
    const int rem = t % (BATCH * NPTS);
    const int b   = rem / NPTS;
    const int j   = rem % NPTS;
    const float* src = (a == 0) ? xyz1 : xyz2;
    float x = src[((size_t)b * NPTS + j) * 3 + 0];
    float y = src[((size_t)b * NPTS + j) * 3 + 1];
    float z = src[((size_t)b * NPTS + j) * 3 + 2];
    int col = g_colid[a][b][j];
    int pos = atomicAdd(&g_cursor[a][b][col], 1);
    g_pts [a][b][pos] = make_float4(x, y, z, x * x + y * y + z * z);
    g_orig[a][b][pos] = j;
}

// ---------------------------------------------------------------------------
// K4: exact NN — one warp per query (65536 warps), lean instruction path.
// Expanding rectangles k in {2,5,12,63} around the query's cell. Lanes stride
// coalesced over each serpentine row-run. Row bounds prefetched LANE-PARALLEL
// (row r's (start,end) in lane r, broadcast by shuffle) for k<=15 (rows<=31);
// the rare k=63 pass uses serial row loads. Hot loop: LDG.128 + 3 FFMA +
// predicated update on strict '<' only — within a lane t increases, so the
// smallest sorted position among equal d survives without a tie compare.
// Cross-lane ties resolved in the warp reduce (min d, then min t).
// bestd/bestt carry across expansions (distances remain valid).
// Exactness: unscanned points lie outside the rect, so they differ from q by
// at least the distance to the nearest rect boundary in x or y (grid-clamped
// sides have no unscanned cells; clamped border cells only push points
// farther). k=63 covers the grid: guaranteed termination.
// ---------------------------------------------------------------------------
__global__ void __launch_bounds__(256)
dacd_nn_kernel() {
    const int lane = threadIdx.x & 31;
    const int w    = blockIdx.x * 8 + (threadIdx.x >> 5);   // 0..65535
    const int dir  = w >> 15;
    const int rm   = w & 32767;
    const int b    = rm >> 13;
    const int si   = rm & 8191;
    const int qarr = 1 - dir;   // dir0 queries = xyz2 (arr 1)
    const int rarr = dir;       // dir0 refs    = xyz1 (arr 0)

    const float4 q  = g_pts [qarr][b][si];
    const int    oi = g_orig[qarr][b][si];
    const float mx = -2.0f * q.x, my = -2.0f * q.y, mz = -2.0f * q.z;
    const int cx0 = cell_coord(q.x);
    const int cy0 = cell_coord(q.y);

    const float4* __restrict__ refs = &g_pts  [rarr][b][0];
    const int*    __restrict__ cs   = &g_start[rarr][b][0];

    const int KS[4] = {2, 5, 12, 63};

    float bestd = INFINITY;   // per-lane: d' = |r|^2 - 2 q.r
    int   bestt = 0;          // per-lane: sorted position of best
    float rd = INFINITY;      // warp-reduced best
    int   rt = 0;

    #pragma unroll 1
    for (int ki = 0; ki < 4; ki++) {
        const int k = KS[ki];
        const int xlo = max(cx0 - k, 0), xhi = min(cx0 + k, GDIM - 1);
        const int ylo = max(cy0 - k, 0), yhi = min(cy0 + k, GDIM - 1);
        const int R   = xhi - xlo + 1;

        if (R <= 32) {
            // lane-parallel row-bound prefetch
            int srow = 0, erow = 0;
            if (lane < R) {
                const int cx = xlo + lane;
                int lo, hi;
                if (cx & 1) { lo = cx * GDIM + (GDIM - 1 - yhi); hi = cx * GDIM + (GDIM - 1 - ylo); }
                else        { lo = cx * GDIM + ylo;              hi = cx * GDIM + yhi; }
                srow = cs[lo];
                erow = cs[hi + 1];
            }
            #pragma unroll 1
            for (int r = 0; r < R; r++) {
                const int s = __shfl_sync(0xFFFFFFFFu, srow, r);
                const int e = __shfl_sync(0xFFFFFFFFu, erow, r);
                for (int t = s + lane; t < e; t += 32) {
                    float4 v = __ldg(&refs[t]);
                    float d = fmaf(mx, v.x, fmaf(my, v.y, fmaf(mz, v.z, v.w)));
                    if (d < bestd) { bestd = d; bestt = t; }
                }
            }
        } else {
            // rare full-coverage pass: serial row bounds
            #pragma unroll 1
            for (int cx = xlo; cx <= xhi; cx++) {
                int lo, hi;
                if (cx & 1) { lo = cx * GDIM + (GDIM - 1 - yhi); hi = cx * GDIM + (GDIM - 1 - ylo); }
                else        { lo = cx * GDIM + ylo;              hi = cx * GDIM + yhi; }
                const int s = cs[lo];
                const int e = cs[hi + 1];
                for (int t = s + lane; t < e; t += 32) {
                    float4 v = __ldg(&refs[t]);
                    float d = fmaf(mx, v.x, fmaf(my, v.y, fmaf(mz, v.z, v.w)));
                    if (d < bestd) { bestd = d; bestt = t; }
                }
            }
        }

        // warp reduce (min d, tie -> min sorted pos)
        rd = bestd; rt = bestt;
        #pragma unroll
        for (int off = 16; off > 0; off >>= 1) {
            float od = __shfl_xor_sync(0xFFFFFFFFu, rd, off);
            int   ot = __shfl_xor_sync(0xFFFFFFFFu, rt, off);
            if (od < rd || (od == rd && ot < rt)) { rd = od; rt = ot; }
        }

        // per-query escape bound
        float sx0 = (xlo > 0)        ? (q.x - cell_lo(xlo))     : BIG;
        float sx1 = (xhi < GDIM - 1) ? (cell_lo(xhi + 1) - q.x) : BIG;
        float sy0 = (ylo > 0)        ? (q.y - cell_lo(ylo))     : BIG;
        float sy1 = (yhi < GDIM - 1) ? (cell_lo(yhi + 1) - q.y) : BIG;
        float bb = fminf(fminf(sx0, sx1), fminf(sy0, sy1));
        const bool covered = (xlo == 0 && ylo == 0 && xhi == GDIM - 1 && yhi == GDIM - 1);
        if ((q.w + rd) <= (bb * bb - MARGIN) || covered) break;
    }

    if (lane == 0) {
        const int bj = g_orig[rarr][b][rt];
        g_dist[dir][b][oi] = q.w + rd;
        g_idx [dir][b][oi] = bj;
        atomicAdd(&g_cnt[dir][b][bj], 1);
    }
}

// ---------------------------------------------------------------------------
// K5: density-aware weighting + reduction to scalar.
// frac_21 = 1.0 exactly; ceil(frac_21) = 1.
// weight1 = 1 / max(1/c + 1e-6, 1),  weight2 = 1 / (c + 1e-6)
// out = sum (1 - exp(-alpha*d) * w) / (2*B*N)
// ---------------------------------------------------------------------------
__global__ void __launch_bounds__(256)
dacd_loss_kernel(float* __restrict__ out) {
    const int t = blockIdx.x * blockDim.x + threadIdx.x;
    const int dir = t / (BATCH * NPTS);
    const int rem = t % (BATCH * NPTS);
    const int b = rem / NPTS;
    const int i = rem % NPTS;

    float dist = g_dist[dir][b][i];
    int   idx  = g_idx [dir][b][i];
    float c    = (float)g_cnt[dir][b][idx];

    float w;
    if (dir == 0) {
        w = 1.0f / fmaxf(1.0f / c + 1e-6f, 1.0f);
    } else {
        w = 1.0f / (c + 1e-6f);
    }

    float e = expf(-dist * ALPHA);
    float contrib = (1.0f - e * w) * (1.0f / (2.0f * BATCH * NPTS));

    #pragma unroll
    for (int off = 16; off > 0; off >>= 1)
        contrib += __shfl_down_sync(0xFFFFFFFFu, contrib, off);

    __shared__ float warp_sums[8];
    const int lane = threadIdx.x & 31;
    const int wid  = threadIdx.x >> 5;
    if (lane == 0) warp_sums[wid] = contrib;
    __syncthreads();

    if (wid == 0) {
        float s = (lane < 8) ? warp_sums[lane] : 0.0f;
        #pragma unroll
        for (int off = 4; off > 0; off >>= 1)
            s += __shfl_down_sync(0xFFFFFFFFu, s, off);
        if (lane == 0) atomicAdd(out, s);
    }
}

// ---------------------------------------------------------------------------
// Launch
// ---------------------------------------------------------------------------
extern "C" void kernel_launch(void* const* d_in, const int* in_sizes, int n_in,
                              void* d_out, int out_size) {
    const float* xyz1 = (const float*)d_in[0];  // prediction [4,8192,3]
    const float* xyz2 = (const float*)d_in[1];  // ground truth [4,8192,3]
    float* out = (float*)d_out;

    (void)in_sizes; (void)n_in; (void)out_size;

    const int total = 2 * BATCH * NPTS;          // 65536

    dacd_hist_kernel    <<<(total + 255) / 256, 256>>>(xyz1, xyz2, out);
    dacd_scan_kernel    <<<2 * BATCH, 1024>>>();
    dacd_scatter_kernel <<<(total + 255) / 256, 256>>>(xyz1, xyz2);

    dacd_nn_kernel<<<total / 8, 256>>>();        // 65536 warps, 1 query each

    dacd_loss_kernel<<<total / 256, 256>>>(out);
}